// round 14
// baseline (speedup 1.0000x reference)
#include <cuda_runtime.h>
#include <cuda_fp16.h>
#include <cstdint>

// ---------------- problem constants ----------------
#define BATCH   16
#define N1      4096
#define N2      1024
#define C2      256
#define OUTCH   256
#define KTOT    4096
#define SPLITK  4
#define KPER    (KTOT/SPLITK)   // 1024
#define KT      64              // K tile
#define NT      (KPER/KT)       // 16 tiles
#define BN_EPS  1e-5f

#define CONVW_BLOCKS 64

// smem (bytes): 3 stages of (W 128x72 halves + B 64x136 halves)
#define WROW_H   72              // 144 B row  (4 mod 32 banks -> LDSM conflict-free)
#define BROW_H   136             // 272 B row  (4 mod 32 banks)
#define WS_BYTES (128*WROW_H*2)  // 18432
#define BS_BYTES (64*BROW_H*2)   // 17408
#define STG_BYTES (WS_BYTES + BS_BYTES)   // 35840
#define SMEM_BYTES (3*STG_BYTES)          // 107520

// ---------------- device scratch ----------------
__device__ int    g_idx[BATCH * N1 * 3];
__device__ float  g_w  [BATCH * N1 * 3];
__device__ __half g_Whf[(size_t)OUTCH * KTOT];                 // 2 MB fp16 W
__device__ __half g_interp[(size_t)BATCH * N1 * C2];           // 33.5 MB fp16 A[b][n][c]
__device__ float  g_yp[SPLITK][(size_t)BATCH * OUTCH * C2];    // 16 MB fp32 partials
__device__ float  g_y [(size_t)BATCH * OUTCH * C2];
__device__ float  g_sum[C2];
__device__ float  g_sumsq[C2];

// ---------------- helpers ----------------
__device__ __forceinline__ uint32_t smem_u32(const void* p) {
    uint32_t a;
    asm("{ .reg .u64 t; cvta.to.shared.u64 t, %1; cvt.u32.u64 %0, t; }" : "=r"(a) : "l"(p));
    return a;
}
__device__ __forceinline__ uint32_t h2_bits(__half2 h) {
    uint32_t u;
    memcpy(&u, &h, 4);
    return u;
}
__device__ __forceinline__ void cp16(uint32_t dst, const void* src) {
    asm volatile("cp.async.cg.shared.global [%0], [%1], 16;" :: "r"(dst), "l"(src) : "memory");
}
#define CP_COMMIT()  asm volatile("cp.async.commit_group;" ::: "memory")
#define CP_WAIT(n)   asm volatile("cp.async.wait_group %0;" :: "n"(n) : "memory")

__device__ __forceinline__ void ldsm_x4(uint32_t* r, uint32_t addr) {
    asm volatile("ldmatrix.sync.aligned.m8n8.x4.shared.b16 {%0,%1,%2,%3}, [%4];"
                 : "=r"(r[0]), "=r"(r[1]), "=r"(r[2]), "=r"(r[3]) : "r"(addr));
}
__device__ __forceinline__ void ldsm_x4_t(uint32_t* r, uint32_t addr) {
    asm volatile("ldmatrix.sync.aligned.m8n8.x4.trans.shared.b16 {%0,%1,%2,%3}, [%4];"
                 : "=r"(r[0]), "=r"(r[1]), "=r"(r[2]), "=r"(r[3]) : "r"(addr));
}
__device__ __forceinline__ void mma_f16(float* d, const uint32_t* a, uint32_t b0, uint32_t b1) {
    asm volatile(
        "mma.sync.aligned.m16n8k16.row.col.f32.f16.f16.f32 "
        "{%0,%1,%2,%3}, {%4,%5,%6,%7}, {%8,%9}, {%0,%1,%2,%3};"
        : "+f"(d[0]), "+f"(d[1]), "+f"(d[2]), "+f"(d[3])
        : "r"(a[0]), "r"(a[1]), "r"(a[2]), "r"(a[3]), "r"(b0), "r"(b1));
}

// ---------------- kernel 1: pre (convW + zero stats | topk) ----------------
// blocks [0,64): W -> fp16 (block 0 also zeroes BN accumulators)
// blocks [64,320): per (b, chunk): 3-NN scan + weights
__global__ __launch_bounds__(256)
void pre_kernel(const float* __restrict__ W1,
                const float* __restrict__ xyz1,
                const float* __restrict__ xyz2) {
    int t = threadIdx.x;

    if (blockIdx.x < CONVW_BLOCKS) {
        if (blockIdx.x == 0) {
            g_sum[t] = 0.f;
            g_sumsq[t] = 0.f;
        }
        const float4* src = (const float4*)W1;
        int base = blockIdx.x * 256 + t;
#pragma unroll
        for (int i = 0; i < 16; ++i) {
            int idx = base + i * (CONVW_BLOCKS * 256);
            float4 v = src[idx];
            __half2 h0 = __floats2half2_rn(v.x, v.y);
            __half2 h1 = __floats2half2_rn(v.z, v.w);
            ((uint2*)g_Whf)[idx] = make_uint2(h2_bits(h0), h2_bits(h1));
        }
        return;
    }

    // ---- topk ----
    __shared__ float4 sq[N2];   // (qx, qy, qz, |q|^2)
    int blk = blockIdx.x - CONVW_BLOCKS;
    int b = blk >> 4;
    int nchunk = blk & 15;

    const float* p2 = xyz2 + (size_t)b * N2 * 3;
    for (int j = t; j < N2; j += 256) {
        float qx = p2[j * 3 + 0], qy = p2[j * 3 + 1], qz = p2[j * 3 + 2];
        sq[j] = make_float4(qx, qy, qz, fmaf(qx, qx, fmaf(qy, qy, qz * qz)));
    }
    __syncthreads();

    int n = nchunk * 256 + t;
    const float* p1 = xyz1 + ((size_t)b * N1 + n) * 3;
    float px = p1[0], py = p1[1], pz = p1[2];
    float px2 = -2.f * px, py2 = -2.f * py, pz2 = -2.f * pz;
    float pp = fmaf(px, px, fmaf(py, py, pz * pz));

    float d0 = 3.4e38f, d1 = 3.4e38f, d2 = 3.4e38f;
    int   i0 = 0, i1 = 0, i2 = 0;
#pragma unroll 8
    for (int j = 0; j < N2; ++j) {
        float4 q = sq[j];
        float d = fmaf(px2, q.x, fmaf(py2, q.y, fmaf(pz2, q.z, q.w)));
        if (d < d2) {
            if (d < d1) {
                d2 = d1; i2 = i1;
                if (d < d0) { d1 = d0; i1 = i0; d0 = d; i0 = j; }
                else        { d1 = d;  i1 = j; }
            } else { d2 = d; i2 = j; }
        }
    }
    float r0 = 1.f / (d0 + pp + 1e-8f);
    float r1 = 1.f / (d1 + pp + 1e-8f);
    float r2 = 1.f / (d2 + pp + 1e-8f);
    float inv = 1.f / (r0 + r1 + r2);
    size_t base = ((size_t)b * N1 + n) * 3;
    g_idx[base + 0] = i0; g_idx[base + 1] = i1; g_idx[base + 2] = i2;
    g_w  [base + 0] = r0 * inv; g_w[base + 1] = r1 * inv; g_w[base + 2] = r2 * inv;
}

// ---------------- kernel 2: interpolation (2 points / thread) -> fp16 ----------------
__global__ void interp_kernel(const float* __restrict__ x2) {
    int pair = threadIdx.x >> 6;            // 0..3
    int lane = threadIdx.x & 63;
    int ptA  = blockIdx.x * 8 + pair * 2;
    int ptB  = ptA + 1;
    int b = ptA >> 12;
    int c = lane * 4;

    size_t baseA = (size_t)ptA * 3, baseB = (size_t)ptB * 3;
    int ai0 = g_idx[baseA + 0], ai1 = g_idx[baseA + 1], ai2 = g_idx[baseA + 2];
    int bi0 = g_idx[baseB + 0], bi1 = g_idx[baseB + 1], bi2 = g_idx[baseB + 2];
    float aw0 = g_w[baseA + 0], aw1 = g_w[baseA + 1], aw2 = g_w[baseA + 2];
    float bw0 = g_w[baseB + 0], bw1 = g_w[baseB + 1], bw2 = g_w[baseB + 2];

    const float* xb = x2 + (size_t)b * N2 * C2 + c;
    float4 a0 = *(const float4*)(xb + (size_t)ai0 * C2);
    float4 a1 = *(const float4*)(xb + (size_t)ai1 * C2);
    float4 a2 = *(const float4*)(xb + (size_t)ai2 * C2);
    float4 b0 = *(const float4*)(xb + (size_t)bi0 * C2);
    float4 b1 = *(const float4*)(xb + (size_t)bi1 * C2);
    float4 b2 = *(const float4*)(xb + (size_t)bi2 * C2);

    __half2 ha0 = __floats2half2_rn(fmaf(aw0, a0.x, fmaf(aw1, a1.x, aw2 * a2.x)),
                                    fmaf(aw0, a0.y, fmaf(aw1, a1.y, aw2 * a2.y)));
    __half2 ha1 = __floats2half2_rn(fmaf(aw0, a0.z, fmaf(aw1, a1.z, aw2 * a2.z)),
                                    fmaf(aw0, a0.w, fmaf(aw1, a1.w, aw2 * a2.w)));
    __half2 hb0 = __floats2half2_rn(fmaf(bw0, b0.x, fmaf(bw1, b1.x, bw2 * b2.x)),
                                    fmaf(bw0, b0.y, fmaf(bw1, b1.y, bw2 * b2.y)));
    __half2 hb1 = __floats2half2_rn(fmaf(bw0, b0.z, fmaf(bw1, b1.z, bw2 * b2.z)),
                                    fmaf(bw0, b0.w, fmaf(bw1, b1.w, bw2 * b2.w)));
    *(uint2*)(g_interp + (size_t)ptA * C2 + c) = make_uint2(h2_bits(ha0), h2_bits(ha1));
    *(uint2*)(g_interp + (size_t)ptB * C2 + c) = make_uint2(h2_bits(hb0), h2_bits(hb1));
}

// ---------------- kernel 3: fp16 m16n8k16 mma GEMM, 3-stage cp.async ----------------
// grid = b(16) x Mtile(2) x Ntile(2) x splitK(4) = 256 CTAs, 256 threads
__global__ __launch_bounds__(256, 2)
void gemm_mma_kernel() {
    extern __shared__ char smc[];
    const uint32_t smb = smem_u32(smc);

    int bid = blockIdx.x;
    int s   = bid & 3;
    int mtb = (bid >> 2) & 1;
    int ntb = (bid >> 3) & 1;
    int b   = bid >> 4;
    int o0 = mtb * 128, c0 = ntb * 128, k0 = s * KPER;

    int t = threadIdx.x;
    int w = t >> 5, lane = t & 31;
    int g = lane >> 2, kq = lane & 3;
    int warp_m = (w & 3) * 32;
    int warp_n = (w >> 2) * 64;

    const __half* Wg = g_Whf + (size_t)o0 * KTOT + k0;
    const __half* Bg = g_interp + ((size_t)b * N1 + k0) * C2 + c0;

    int wr[4], wc[4], br[4], bc[4];
    uint32_t wdst[4], bdst[4];
#pragma unroll
    for (int i = 0; i < 4; ++i) {
        int li = i * 256 + t;
        wr[i] = li >> 3;  wc[i] = li & 7;
        br[i] = li >> 4;  bc[i] = li & 15;
        wdst[i] = (uint32_t)(wr[i] * (WROW_H * 2) + wc[i] * 16);
        bdst[i] = (uint32_t)(WS_BYTES + br[i] * (BROW_H * 2) + bc[i] * 16);
    }

    int sel = lane >> 3, li8 = lane & 7;
    uint32_t aoff = (uint32_t)(((warp_m + li8 + (sel & 1) * 8) * WROW_H + (sel >> 1) * 8) * 2);
    uint32_t boff = (uint32_t)(WS_BYTES +
                    ((li8 + (sel & 1) * 8) * BROW_H + warp_n + (sel >> 1) * 8) * 2);

    float acc[2][8][4];
#pragma unroll
    for (int mt = 0; mt < 2; ++mt)
#pragma unroll
        for (int nt = 0; nt < 8; ++nt)
#pragma unroll
            for (int r = 0; r < 4; ++r) acc[mt][nt][r] = 0.f;

#pragma unroll
    for (int pre = 0; pre < 2; ++pre) {
        uint32_t sb = smb + (uint32_t)(pre * STG_BYTES);
        int kg = pre * KT;
#pragma unroll
        for (int i = 0; i < 4; ++i) {
            cp16(sb + wdst[i], Wg + (size_t)wr[i] * KTOT + kg + wc[i] * 8);
            cp16(sb + bdst[i], Bg + (size_t)(kg + br[i]) * C2 + bc[i] * 8);
        }
        CP_COMMIT();
    }

    int cur = 0;
    int nxt2 = 2 * STG_BYTES;
    for (int kt = 0; kt < NT; ++kt) {
        if (kt == NT - 1) { CP_WAIT(0); } else { CP_WAIT(1); }
        __syncthreads();

        if (kt + 2 < NT) {
            uint32_t sb = smb + (uint32_t)nxt2;
            int kg = (kt + 2) * KT;
#pragma unroll
            for (int i = 0; i < 4; ++i) {
                cp16(sb + wdst[i], Wg + (size_t)wr[i] * KTOT + kg + wc[i] * 8);
                cp16(sb + bdst[i], Bg + (size_t)(kg + br[i]) * C2 + bc[i] * 8);
            }
            CP_COMMIT();
        }

#pragma unroll
        for (int ks = 0; ks < 4; ++ks) {           // 4 x k16 per tile
            uint32_t a0[4], a1[4];
            uint32_t abase = smb + (uint32_t)cur + aoff + (uint32_t)(ks * 32);
            ldsm_x4(a0, abase);
            ldsm_x4(a1, abase + 16 * WROW_H * 2);
            uint32_t bbase = smb + (uint32_t)cur + boff + (uint32_t)(ks * 16 * BROW_H * 2);
#pragma unroll
            for (int p = 0; p < 4; ++p) {          // n-chunk pairs (16 cols each)
                uint32_t r[4];
                ldsm_x4_t(r, bbase + (uint32_t)(p * 32));
                mma_f16(acc[0][2 * p],     a0, r[0], r[1]);
                mma_f16(acc[1][2 * p],     a1, r[0], r[1]);
                mma_f16(acc[0][2 * p + 1], a0, r[2], r[3]);
                mma_f16(acc[1][2 * p + 1], a1, r[2], r[3]);
            }
        }

        cur  += STG_BYTES; if (cur  == 3 * STG_BYTES) cur  = 0;
        nxt2 += STG_BYTES; if (nxt2 == 3 * STG_BYTES) nxt2 = 0;
    }

    // epilogue -> g_yp[s]
    float* out = g_yp[s] + ((size_t)b * OUTCH + o0) * C2 + c0;
#pragma unroll
    for (int mt = 0; mt < 2; ++mt) {
        int r0 = warp_m + mt * 16 + g;
#pragma unroll
        for (int nt = 0; nt < 8; ++nt) {
            int col = warp_n + nt * 8 + kq * 2;
            *(float2*)(out + (size_t)r0 * C2 + col)       = make_float2(acc[mt][nt][0], acc[mt][nt][1]);
            *(float2*)(out + (size_t)(r0 + 8) * C2 + col) = make_float2(acc[mt][nt][2], acc[mt][nt][3]);
        }
    }
}

// ---------------- kernel 4: reduce partials + bias + BN stats (float4) ----------------
// block = 16 rows; thread t: channel quad (t&63)*4, row subset (t>>6) + 4k
__global__ void reduce_kernel(const float* __restrict__ b1) {
    int t = threadIdx.x;
    int cq = (t & 63) * 4;
    int rsub = t >> 6;        // 0..3
    int row0 = blockIdx.x * 16;

    float4 s1 = make_float4(0.f, 0.f, 0.f, 0.f);
    float4 s2 = make_float4(0.f, 0.f, 0.f, 0.f);
#pragma unroll
    for (int r = rsub; r < 16; r += 4) {
        int row = row0 + r;
        float bias = b1[row & (OUTCH - 1)];
        size_t idx = ((size_t)row * C2 + cq) >> 2;   // float4 index
        float4 v = make_float4(bias, bias, bias, bias);
#pragma unroll
        for (int s = 0; s < SPLITK; ++s) {
            float4 p = ((const float4*)g_yp[s])[idx];
            v.x += p.x; v.y += p.y; v.z += p.z; v.w += p.w;
        }
        ((float4*)g_y)[idx] = v;
        s1.x += v.x; s1.y += v.y; s1.z += v.z; s1.w += v.w;
        s2.x = fmaf(v.x, v.x, s2.x); s2.y = fmaf(v.y, v.y, s2.y);
        s2.z = fmaf(v.z, v.z, s2.z); s2.w = fmaf(v.w, v.w, s2.w);
    }
    atomicAdd(&g_sum[cq + 0], s1.x); atomicAdd(&g_sum[cq + 1], s1.y);
    atomicAdd(&g_sum[cq + 2], s1.z); atomicAdd(&g_sum[cq + 3], s1.w);
    atomicAdd(&g_sumsq[cq + 0], s2.x); atomicAdd(&g_sumsq[cq + 1], s2.y);
    atomicAdd(&g_sumsq[cq + 2], s2.z); atomicAdd(&g_sumsq[cq + 3], s2.w);
}

// ---------------- kernel 5: BN + ReLU (float4) ----------------
// 256 blocks x 256 threads x 4 float4 = 1M floats
__global__ void bn_kernel(const float* __restrict__ gamma,
                          const float* __restrict__ beta,
                          float* __restrict__ out) {
    const float invN = 1.f / (BATCH * OUTCH);
#pragma unroll
    for (int i = 0; i < 4; ++i) {
        int idx4 = (blockIdx.x * 4 + i) * 256 + threadIdx.x;  // float4 index
        int cq = (idx4 & 63) * 4;
        float4 sm = *(const float4*)(g_sum + cq);
        float4 sq = *(const float4*)(g_sumsq + cq);
        float4 gm = *(const float4*)(gamma + cq);
        float4 bt = *(const float4*)(beta + cq);
        float4 v  = ((const float4*)g_y)[idx4];
        float4 r;
        {
            float mean = sm.x * invN, var = fmaf(sq.x, invN, -mean * mean);
            r.x = fmaxf(fmaf(gm.x * rsqrtf(var + BN_EPS), v.x - mean, bt.x), 0.f);
        }
        {
            float mean = sm.y * invN, var = fmaf(sq.y, invN, -mean * mean);
            r.y = fmaxf(fmaf(gm.y * rsqrtf(var + BN_EPS), v.y - mean, bt.y), 0.f);
        }
        {
            float mean = sm.z * invN, var = fmaf(sq.z, invN, -mean * mean);
            r.z = fmaxf(fmaf(gm.z * rsqrtf(var + BN_EPS), v.z - mean, bt.z), 0.f);
        }
        {
            float mean = sm.w * invN, var = fmaf(sq.w, invN, -mean * mean);
            r.w = fmaxf(fmaf(gm.w * rsqrtf(var + BN_EPS), v.w - mean, bt.w), 0.f);
        }
        ((float4*)out)[idx4] = r;
    }
}

// ---------------- launcher ----------------
extern "C" void kernel_launch(void* const* d_in, const int* in_sizes, int n_in,
                              void* d_out, int out_size) {
    const float* x2    = (const float*)d_in[1];
    const float* xyz1  = (const float*)d_in[2];
    const float* xyz2  = (const float*)d_in[3];
    const float* W1    = (const float*)d_in[4];
    const float* b1    = (const float*)d_in[5];
    const float* gamma = (const float*)d_in[6];
    const float* beta  = (const float*)d_in[7];
    float* out = (float*)d_out;

    cudaFuncSetAttribute(gemm_mma_kernel,
                         cudaFuncAttributeMaxDynamicSharedMemorySize,
                         SMEM_BYTES);

    pre_kernel<<<CONVW_BLOCKS + BATCH * 16, 256>>>(W1, xyz1, xyz2);
    interp_kernel<<<(BATCH * N1) / 8, 256>>>(x2);
    gemm_mma_kernel<<<BATCH * 2 * 2 * SPLITK, 256, SMEM_BYTES>>>();
    reduce_kernel<<<(BATCH * OUTCH) / 16, 256>>>(b1);
    bn_kernel<<<256, 256>>>(gamma, beta, out);
}

// round 15
// speedup vs baseline: 1.2621x; 1.2621x over previous
#include <cuda_runtime.h>
#include <cuda_fp16.h>
#include <cstdint>

// ---------------- problem constants ----------------
#define BATCH   16
#define N1      4096
#define N2      1024
#define C2      256
#define OUTCH   256
#define KTOT    4096
#define SPLITK  4
#define KPER    (KTOT/SPLITK)   // 1024
#define KT      64              // K tile
#define NT      (KPER/KT)       // 16 tiles
#define BN_EPS  1e-5f

#define CONVW_BLOCKS 64

// smem (bytes): 3 stages of (W 128x72 halves + B 64x136 halves)
#define WROW_H   72              // 144 B row  (4 mod 32 banks -> LDSM conflict-free)
#define BROW_H   136             // 272 B row  (4 mod 32 banks)
#define WS_BYTES (128*WROW_H*2)  // 18432
#define BS_BYTES (64*BROW_H*2)   // 17408
#define STG_BYTES (WS_BYTES + BS_BYTES)   // 35840
#define SMEM_BYTES (3*STG_BYTES)          // 107520

// ---------------- device scratch ----------------
__device__ int    g_idx[BATCH * N1 * 3];
__device__ float  g_w  [BATCH * N1 * 3];
__device__ __half g_Whf[(size_t)OUTCH * KTOT];                 // 2 MB fp16 W
__device__ __half g_interp[(size_t)BATCH * N1 * C2];           // 33.5 MB fp16 A[b][n][c]
__device__ float  g_yp[SPLITK][(size_t)BATCH * OUTCH * C2];    // 16 MB fp32 partials
__device__ float  g_y [(size_t)BATCH * OUTCH * C2];
__device__ float  g_sum[C2];
__device__ float  g_sumsq[C2];

// ---------------- helpers ----------------
__device__ __forceinline__ uint32_t smem_u32(const void* p) {
    uint32_t a;
    asm("{ .reg .u64 t; cvta.to.shared.u64 t, %1; cvt.u32.u64 %0, t; }" : "=r"(a) : "l"(p));
    return a;
}
__device__ __forceinline__ uint32_t h2_bits(__half2 h) {
    uint32_t u;
    memcpy(&u, &h, 4);
    return u;
}
__device__ __forceinline__ void cp16(uint32_t dst, const void* src) {
    asm volatile("cp.async.cg.shared.global [%0], [%1], 16;" :: "r"(dst), "l"(src) : "memory");
}
#define CP_COMMIT()  asm volatile("cp.async.commit_group;" ::: "memory")
#define CP_WAIT(n)   asm volatile("cp.async.wait_group %0;" :: "n"(n) : "memory")

__device__ __forceinline__ void ldsm_x4(uint32_t* r, uint32_t addr) {
    asm volatile("ldmatrix.sync.aligned.m8n8.x4.shared.b16 {%0,%1,%2,%3}, [%4];"
                 : "=r"(r[0]), "=r"(r[1]), "=r"(r[2]), "=r"(r[3]) : "r"(addr));
}
__device__ __forceinline__ void ldsm_x4_t(uint32_t* r, uint32_t addr) {
    asm volatile("ldmatrix.sync.aligned.m8n8.x4.trans.shared.b16 {%0,%1,%2,%3}, [%4];"
                 : "=r"(r[0]), "=r"(r[1]), "=r"(r[2]), "=r"(r[3]) : "r"(addr));
}
__device__ __forceinline__ void mma_f16(float* d, const uint32_t* a, uint32_t b0, uint32_t b1) {
    asm volatile(
        "mma.sync.aligned.m16n8k16.row.col.f32.f16.f16.f32 "
        "{%0,%1,%2,%3}, {%4,%5,%6,%7}, {%8,%9}, {%0,%1,%2,%3};"
        : "+f"(d[0]), "+f"(d[1]), "+f"(d[2]), "+f"(d[3])
        : "r"(a[0]), "r"(a[1]), "r"(a[2]), "r"(a[3]), "r"(b0), "r"(b1));
}

// ---------------- kernel 1: pre (convW + zero stats | topk) ----------------
// blocks [0,64): W -> fp16 (block 0 also zeroes BN accumulators)
// blocks [64,320): per (b, chunk): 3-NN scan + weights
__global__ __launch_bounds__(256)
void pre_kernel(const float* __restrict__ W1,
                const float* __restrict__ xyz1,
                const float* __restrict__ xyz2) {
    int t = threadIdx.x;

    if (blockIdx.x < CONVW_BLOCKS) {
        if (blockIdx.x == 0) {
            g_sum[t] = 0.f;
            g_sumsq[t] = 0.f;
        }
        const float4* src = (const float4*)W1;
        int base = blockIdx.x * 256 + t;
#pragma unroll
        for (int i = 0; i < 16; ++i) {
            int idx = base + i * (CONVW_BLOCKS * 256);
            float4 v = src[idx];
            __half2 h0 = __floats2half2_rn(v.x, v.y);
            __half2 h1 = __floats2half2_rn(v.z, v.w);
            ((uint2*)g_Whf)[idx] = make_uint2(h2_bits(h0), h2_bits(h1));
        }
        return;
    }

    // ---- topk ----
    __shared__ float4 sq[N2];   // (qx, qy, qz, |q|^2)
    int blk = blockIdx.x - CONVW_BLOCKS;
    int b = blk >> 4;
    int nchunk = blk & 15;

    const float* p2 = xyz2 + (size_t)b * N2 * 3;
    for (int j = t; j < N2; j += 256) {
        float qx = p2[j * 3 + 0], qy = p2[j * 3 + 1], qz = p2[j * 3 + 2];
        sq[j] = make_float4(qx, qy, qz, fmaf(qx, qx, fmaf(qy, qy, qz * qz)));
    }
    __syncthreads();

    int n = nchunk * 256 + t;
    const float* p1 = xyz1 + ((size_t)b * N1 + n) * 3;
    float px = p1[0], py = p1[1], pz = p1[2];
    float px2 = -2.f * px, py2 = -2.f * py, pz2 = -2.f * pz;
    float pp = fmaf(px, px, fmaf(py, py, pz * pz));

    float d0 = 3.4e38f, d1 = 3.4e38f, d2 = 3.4e38f;
    int   i0 = 0, i1 = 0, i2 = 0;
#pragma unroll 8
    for (int j = 0; j < N2; ++j) {
        float4 q = sq[j];
        float d = fmaf(px2, q.x, fmaf(py2, q.y, fmaf(pz2, q.z, q.w)));
        if (d < d2) {
            if (d < d1) {
                d2 = d1; i2 = i1;
                if (d < d0) { d1 = d0; i1 = i0; d0 = d; i0 = j; }
                else        { d1 = d;  i1 = j; }
            } else { d2 = d; i2 = j; }
        }
    }
    float r0 = 1.f / (d0 + pp + 1e-8f);
    float r1 = 1.f / (d1 + pp + 1e-8f);
    float r2 = 1.f / (d2 + pp + 1e-8f);
    float inv = 1.f / (r0 + r1 + r2);
    size_t base = ((size_t)b * N1 + n) * 3;
    g_idx[base + 0] = i0; g_idx[base + 1] = i1; g_idx[base + 2] = i2;
    g_w  [base + 0] = r0 * inv; g_w[base + 1] = r1 * inv; g_w[base + 2] = r2 * inv;
}

// ---------------- kernel 2: interpolation (2 points / thread) -> fp16 ----------------
__global__ void interp_kernel(const float* __restrict__ x2) {
    int pair = threadIdx.x >> 6;            // 0..3
    int lane = threadIdx.x & 63;
    int ptA  = blockIdx.x * 8 + pair * 2;
    int ptB  = ptA + 1;
    int b = ptA >> 12;
    int c = lane * 4;

    size_t baseA = (size_t)ptA * 3, baseB = (size_t)ptB * 3;
    int ai0 = g_idx[baseA + 0], ai1 = g_idx[baseA + 1], ai2 = g_idx[baseA + 2];
    int bi0 = g_idx[baseB + 0], bi1 = g_idx[baseB + 1], bi2 = g_idx[baseB + 2];
    float aw0 = g_w[baseA + 0], aw1 = g_w[baseA + 1], aw2 = g_w[baseA + 2];
    float bw0 = g_w[baseB + 0], bw1 = g_w[baseB + 1], bw2 = g_w[baseB + 2];

    const float* xb = x2 + (size_t)b * N2 * C2 + c;
    float4 a0 = *(const float4*)(xb + (size_t)ai0 * C2);
    float4 a1 = *(const float4*)(xb + (size_t)ai1 * C2);
    float4 a2 = *(const float4*)(xb + (size_t)ai2 * C2);
    float4 b0 = *(const float4*)(xb + (size_t)bi0 * C2);
    float4 b1 = *(const float4*)(xb + (size_t)bi1 * C2);
    float4 b2 = *(const float4*)(xb + (size_t)bi2 * C2);

    __half2 ha0 = __floats2half2_rn(fmaf(aw0, a0.x, fmaf(aw1, a1.x, aw2 * a2.x)),
                                    fmaf(aw0, a0.y, fmaf(aw1, a1.y, aw2 * a2.y)));
    __half2 ha1 = __floats2half2_rn(fmaf(aw0, a0.z, fmaf(aw1, a1.z, aw2 * a2.z)),
                                    fmaf(aw0, a0.w, fmaf(aw1, a1.w, aw2 * a2.w)));
    __half2 hb0 = __floats2half2_rn(fmaf(bw0, b0.x, fmaf(bw1, b1.x, bw2 * b2.x)),
                                    fmaf(bw0, b0.y, fmaf(bw1, b1.y, bw2 * b2.y)));
    __half2 hb1 = __floats2half2_rn(fmaf(bw0, b0.z, fmaf(bw1, b1.z, bw2 * b2.z)),
                                    fmaf(bw0, b0.w, fmaf(bw1, b1.w, bw2 * b2.w)));
    *(uint2*)(g_interp + (size_t)ptA * C2 + c) = make_uint2(h2_bits(ha0), h2_bits(ha1));
    *(uint2*)(g_interp + (size_t)ptB * C2 + c) = make_uint2(h2_bits(hb0), h2_bits(hb1));
}

// ---------------- kernel 3: fp16 m16n8k16 mma GEMM, 3-stage cp.async ----------------
// grid = b(16) x Mtile(2) x Ntile(2) x splitK(4) = 256 CTAs, 256 threads
__global__ __launch_bounds__(256, 2)
void gemm_mma_kernel() {
    extern __shared__ char smc[];
    const uint32_t smb = smem_u32(smc);

    int bid = blockIdx.x;
    int s   = bid & 3;
    int mtb = (bid >> 2) & 1;
    int ntb = (bid >> 3) & 1;
    int b   = bid >> 4;
    int o0 = mtb * 128, c0 = ntb * 128, k0 = s * KPER;

    int t = threadIdx.x;
    int w = t >> 5, lane = t & 31;
    int g = lane >> 2, kq = lane & 3;
    int warp_m = (w & 3) * 32;
    int warp_n = (w >> 2) * 64;

    const __half* Wg = g_Whf + (size_t)o0 * KTOT + k0;
    const __half* Bg = g_interp + ((size_t)b * N1 + k0) * C2 + c0;

    int wr[4], wc[4], br[4], bc[4];
    uint32_t wdst[4], bdst[4];
#pragma unroll
    for (int i = 0; i < 4; ++i) {
        int li = i * 256 + t;
        wr[i] = li >> 3;  wc[i] = li & 7;
        br[i] = li >> 4;  bc[i] = li & 15;
        wdst[i] = (uint32_t)(wr[i] * (WROW_H * 2) + wc[i] * 16);
        bdst[i] = (uint32_t)(WS_BYTES + br[i] * (BROW_H * 2) + bc[i] * 16);
    }

    int sel = lane >> 3, li8 = lane & 7;
    uint32_t aoff = (uint32_t)(((warp_m + li8 + (sel & 1) * 8) * WROW_H + (sel >> 1) * 8) * 2);
    uint32_t boff = (uint32_t)(WS_BYTES +
                    ((li8 + (sel & 1) * 8) * BROW_H + warp_n + (sel >> 1) * 8) * 2);

    float acc[2][8][4];
#pragma unroll
    for (int mt = 0; mt < 2; ++mt)
#pragma unroll
        for (int nt = 0; nt < 8; ++nt)
#pragma unroll
            for (int r = 0; r < 4; ++r) acc[mt][nt][r] = 0.f;

#pragma unroll
    for (int pre = 0; pre < 2; ++pre) {
        uint32_t sb = smb + (uint32_t)(pre * STG_BYTES);
        int kg = pre * KT;
#pragma unroll
        for (int i = 0; i < 4; ++i) {
            cp16(sb + wdst[i], Wg + (size_t)wr[i] * KTOT + kg + wc[i] * 8);
            cp16(sb + bdst[i], Bg + (size_t)(kg + br[i]) * C2 + bc[i] * 8);
        }
        CP_COMMIT();
    }

    int cur = 0;
    int nxt2 = 2 * STG_BYTES;
    for (int kt = 0; kt < NT; ++kt) {
        if (kt == NT - 1) { CP_WAIT(0); } else { CP_WAIT(1); }
        __syncthreads();

        if (kt + 2 < NT) {
            uint32_t sb = smb + (uint32_t)nxt2;
            int kg = (kt + 2) * KT;
#pragma unroll
            for (int i = 0; i < 4; ++i) {
                cp16(sb + wdst[i], Wg + (size_t)wr[i] * KTOT + kg + wc[i] * 8);
                cp16(sb + bdst[i], Bg + (size_t)(kg + br[i]) * C2 + bc[i] * 8);
            }
            CP_COMMIT();
        }

#pragma unroll
        for (int ks = 0; ks < 4; ++ks) {           // 4 x k16 per tile
            uint32_t a0[4], a1[4];
            uint32_t abase = smb + (uint32_t)cur + aoff + (uint32_t)(ks * 32);
            ldsm_x4(a0, abase);
            ldsm_x4(a1, abase + 16 * WROW_H * 2);
            uint32_t bbase = smb + (uint32_t)cur + boff + (uint32_t)(ks * 16 * BROW_H * 2);
#pragma unroll
            for (int p = 0; p < 4; ++p) {          // n-chunk pairs (16 cols each)
                uint32_t r[4];
                ldsm_x4_t(r, bbase + (uint32_t)(p * 32));
                mma_f16(acc[0][2 * p],     a0, r[0], r[1]);
                mma_f16(acc[1][2 * p],     a1, r[0], r[1]);
                mma_f16(acc[0][2 * p + 1], a0, r[2], r[3]);
                mma_f16(acc[1][2 * p + 1], a1, r[2], r[3]);
            }
        }

        cur  += STG_BYTES; if (cur  == 3 * STG_BYTES) cur  = 0;
        nxt2 += STG_BYTES; if (nxt2 == 3 * STG_BYTES) nxt2 = 0;
    }

    // epilogue -> g_yp[s]
    float* out = g_yp[s] + ((size_t)b * OUTCH + o0) * C2 + c0;
#pragma unroll
    for (int mt = 0; mt < 2; ++mt) {
        int r0 = warp_m + mt * 16 + g;
#pragma unroll
        for (int nt = 0; nt < 8; ++nt) {
            int col = warp_n + nt * 8 + kq * 2;
            *(float2*)(out + (size_t)r0 * C2 + col)       = make_float2(acc[mt][nt][0], acc[mt][nt][1]);
            *(float2*)(out + (size_t)(r0 + 8) * C2 + col) = make_float2(acc[mt][nt][2], acc[mt][nt][3]);
        }
    }
}

// ---------------- kernel 4: reduce partials + bias + BN stats (r13 scalar form) ----------------
__global__ void reduce_kernel(const float* __restrict__ b1) {
    int c = threadIdx.x;
    int row0 = blockIdx.x * 16;
    float s1 = 0.f, s2 = 0.f;
    for (int r = 0; r < 16; ++r) {
        int row = row0 + r;
        int o = row & (OUTCH - 1);
        size_t idx = (size_t)row * C2 + c;
        float v = b1[o];
#pragma unroll
        for (int s = 0; s < SPLITK; ++s) v += g_yp[s][idx];
        g_y[idx] = v;
        s1 += v;
        s2 = fmaf(v, v, s2);
    }
    atomicAdd(&g_sum[c], s1);
    atomicAdd(&g_sumsq[c], s2);
}

// ---------------- kernel 5: BN + ReLU (r13 scalar form) ----------------
__global__ void bn_kernel(const float* __restrict__ gamma,
                          const float* __restrict__ beta,
                          float* __restrict__ out) {
    int c = threadIdx.x;
    int row = blockIdx.x;
    const float invN = 1.f / (BATCH * OUTCH);
    float mean = g_sum[c] * invN;
    float var  = fmaf(g_sumsq[c], invN, -mean * mean);
    float rstd = rsqrtf(var + BN_EPS);
    float v = g_y[(size_t)row * C2 + c];
    float r = fmaf(gamma[c] * rstd, v - mean, beta[c]);
    out[(size_t)row * C2 + c] = fmaxf(r, 0.f);
}

// ---------------- launcher ----------------
extern "C" void kernel_launch(void* const* d_in, const int* in_sizes, int n_in,
                              void* d_out, int out_size) {
    const float* x2    = (const float*)d_in[1];
    const float* xyz1  = (const float*)d_in[2];
    const float* xyz2  = (const float*)d_in[3];
    const float* W1    = (const float*)d_in[4];
    const float* b1    = (const float*)d_in[5];
    const float* gamma = (const float*)d_in[6];
    const float* beta  = (const float*)d_in[7];
    float* out = (float*)d_out;

    cudaFuncSetAttribute(gemm_mma_kernel,
                         cudaFuncAttributeMaxDynamicSharedMemorySize,
                         SMEM_BYTES);

    pre_kernel<<<CONVW_BLOCKS + BATCH * 16, 256>>>(W1, xyz1, xyz2);
    interp_kernel<<<(BATCH * N1) / 8, 256>>>(x2);
    gemm_mma_kernel<<<BATCH * 2 * 2 * SPLITK, 256, SMEM_BYTES>>>();
    reduce_kernel<<<(BATCH * OUTCH) / 16, C2>>>(b1);
    bn_kernel<<<BATCH * OUTCH, C2>>>(gamma, beta, out);
}

// round 16
// speedup vs baseline: 1.4330x; 1.1355x over previous
#include <cuda_runtime.h>
#include <cuda_fp16.h>
#include <cstdint>

// ---------------- problem constants ----------------
#define BATCH   16
#define N1      4096
#define N2      1024
#define C2      256
#define OUTCH   256
#define KTOT    4096
#define SPLITK  4
#define KPER    (KTOT/SPLITK)   // 1024
#define KT      64              // K tile
#define NT      (KPER/KT)       // 16 tiles
#define BN_EPS  1e-5f

#define RB_BLOCKS 256           // reduce+bn grid

// smem (bytes): 3 stages of (W 128x72 halves + B 64x136 halves)
#define WROW_H   72              // 144 B row  (4 mod 32 banks -> LDSM conflict-free)
#define BROW_H   136             // 272 B row  (4 mod 32 banks)
#define WS_BYTES (128*WROW_H*2)  // 18432
#define BS_BYTES (64*BROW_H*2)   // 17408
#define STG_BYTES (WS_BYTES + BS_BYTES)   // 35840
#define SMEM_BYTES (3*STG_BYTES)          // 107520

// ---------------- device scratch ----------------
__device__ int    g_idx[BATCH * N1 * 3];
__device__ float  g_w  [BATCH * N1 * 3];
__device__ __half g_Whf[(size_t)OUTCH * KTOT];                 // 2 MB fp16 W
__device__ __half g_interp[(size_t)BATCH * N1 * C2];           // 33.5 MB fp16 A[b][n][c]
__device__ float  g_yp[SPLITK][(size_t)BATCH * OUTCH * C2];    // 16 MB fp32 partials
__device__ float  g_sum[C2];
__device__ float  g_sumsq[C2];
__device__ unsigned int g_cnt;

// ---------------- helpers ----------------
__device__ __forceinline__ uint32_t smem_u32(const void* p) {
    uint32_t a;
    asm("{ .reg .u64 t; cvta.to.shared.u64 t, %1; cvt.u32.u64 %0, t; }" : "=r"(a) : "l"(p));
    return a;
}
__device__ __forceinline__ uint32_t h2_bits(__half2 h) {
    uint32_t u;
    memcpy(&u, &h, 4);
    return u;
}
__device__ __forceinline__ void cp16(uint32_t dst, const void* src) {
    asm volatile("cp.async.cg.shared.global [%0], [%1], 16;" :: "r"(dst), "l"(src) : "memory");
}
#define CP_COMMIT()  asm volatile("cp.async.commit_group;" ::: "memory")
#define CP_WAIT(n)   asm volatile("cp.async.wait_group %0;" :: "n"(n) : "memory")

__device__ __forceinline__ void ldsm_x4(uint32_t* r, uint32_t addr) {
    asm volatile("ldmatrix.sync.aligned.m8n8.x4.shared.b16 {%0,%1,%2,%3}, [%4];"
                 : "=r"(r[0]), "=r"(r[1]), "=r"(r[2]), "=r"(r[3]) : "r"(addr));
}
__device__ __forceinline__ void ldsm_x4_t(uint32_t* r, uint32_t addr) {
    asm volatile("ldmatrix.sync.aligned.m8n8.x4.trans.shared.b16 {%0,%1,%2,%3}, [%4];"
                 : "=r"(r[0]), "=r"(r[1]), "=r"(r[2]), "=r"(r[3]) : "r"(addr));
}
__device__ __forceinline__ void mma_f16(float* d, const uint32_t* a, uint32_t b0, uint32_t b1) {
    asm volatile(
        "mma.sync.aligned.m16n8k16.row.col.f32.f16.f16.f32 "
        "{%0,%1,%2,%3}, {%4,%5,%6,%7}, {%8,%9}, {%0,%1,%2,%3};"
        : "+f"(d[0]), "+f"(d[1]), "+f"(d[2]), "+f"(d[3])
        : "r"(a[0]), "r"(a[1]), "r"(a[2]), "r"(a[3]), "r"(b0), "r"(b1));
}

// ---------------- kernel 0: W -> fp16 copy + BN accumulator/counter zeroing ----------------
__global__ void convW_kernel(const float* __restrict__ W1) {
    if (blockIdx.x == 0) {
        g_sum[threadIdx.x] = 0.f;
        g_sumsq[threadIdx.x] = 0.f;
        if (threadIdx.x == 0) g_cnt = 0u;
    }
    int i = blockIdx.x * 256 + threadIdx.x;   // float4 index
    float4 v = ((const float4*)W1)[i];
    __half2 h0 = __floats2half2_rn(v.x, v.y);
    __half2 h1 = __floats2half2_rn(v.z, v.w);
    ((uint2*)g_Whf)[i] = make_uint2(h2_bits(h0), h2_bits(h1));
}

// ---------------- kernel 1: 3-NN + weights (dot-product form, packed smem) ----------------
__global__ void topk_kernel(const float* __restrict__ xyz1,
                            const float* __restrict__ xyz2) {
    __shared__ float4 sq[N2];   // (qx, qy, qz, |q|^2)
    int b = blockIdx.x >> 4;
    int nchunk = blockIdx.x & 15;

    const float* p2 = xyz2 + (size_t)b * N2 * 3;
    for (int j = threadIdx.x; j < N2; j += 256) {
        float qx = p2[j * 3 + 0], qy = p2[j * 3 + 1], qz = p2[j * 3 + 2];
        sq[j] = make_float4(qx, qy, qz, fmaf(qx, qx, fmaf(qy, qy, qz * qz)));
    }
    __syncthreads();

    int n = nchunk * 256 + threadIdx.x;
    const float* p1 = xyz1 + ((size_t)b * N1 + n) * 3;
    float px = p1[0], py = p1[1], pz = p1[2];
    float px2 = -2.f * px, py2 = -2.f * py, pz2 = -2.f * pz;
    float pp = fmaf(px, px, fmaf(py, py, pz * pz));

    float d0 = 3.4e38f, d1 = 3.4e38f, d2 = 3.4e38f;
    int   i0 = 0, i1 = 0, i2 = 0;
#pragma unroll 8
    for (int j = 0; j < N2; ++j) {
        float4 q = sq[j];
        float d = fmaf(px2, q.x, fmaf(py2, q.y, fmaf(pz2, q.z, q.w)));
        if (d < d2) {
            if (d < d1) {
                d2 = d1; i2 = i1;
                if (d < d0) { d1 = d0; i1 = i0; d0 = d; i0 = j; }
                else        { d1 = d;  i1 = j; }
            } else { d2 = d; i2 = j; }
        }
    }
    float r0 = 1.f / (d0 + pp + 1e-8f);
    float r1 = 1.f / (d1 + pp + 1e-8f);
    float r2 = 1.f / (d2 + pp + 1e-8f);
    float inv = 1.f / (r0 + r1 + r2);
    size_t base = ((size_t)b * N1 + n) * 3;
    g_idx[base + 0] = i0; g_idx[base + 1] = i1; g_idx[base + 2] = i2;
    g_w  [base + 0] = r0 * inv; g_w[base + 1] = r1 * inv; g_w[base + 2] = r2 * inv;
}

// ---------------- kernel 2: interpolation (2 points / thread) -> fp16 ----------------
__global__ void interp_kernel(const float* __restrict__ x2) {
    int pair = threadIdx.x >> 6;            // 0..3
    int lane = threadIdx.x & 63;
    int ptA  = blockIdx.x * 8 + pair * 2;
    int ptB  = ptA + 1;
    int b = ptA >> 12;
    int c = lane * 4;

    size_t baseA = (size_t)ptA * 3, baseB = (size_t)ptB * 3;
    int ai0 = g_idx[baseA + 0], ai1 = g_idx[baseA + 1], ai2 = g_idx[baseA + 2];
    int bi0 = g_idx[baseB + 0], bi1 = g_idx[baseB + 1], bi2 = g_idx[baseB + 2];
    float aw0 = g_w[baseA + 0], aw1 = g_w[baseA + 1], aw2 = g_w[baseA + 2];
    float bw0 = g_w[baseB + 0], bw1 = g_w[baseB + 1], bw2 = g_w[baseB + 2];

    const float* xb = x2 + (size_t)b * N2 * C2 + c;
    float4 a0 = *(const float4*)(xb + (size_t)ai0 * C2);
    float4 a1 = *(const float4*)(xb + (size_t)ai1 * C2);
    float4 a2 = *(const float4*)(xb + (size_t)ai2 * C2);
    float4 b0 = *(const float4*)(xb + (size_t)bi0 * C2);
    float4 b1 = *(const float4*)(xb + (size_t)bi1 * C2);
    float4 b2 = *(const float4*)(xb + (size_t)bi2 * C2);

    __half2 ha0 = __floats2half2_rn(fmaf(aw0, a0.x, fmaf(aw1, a1.x, aw2 * a2.x)),
                                    fmaf(aw0, a0.y, fmaf(aw1, a1.y, aw2 * a2.y)));
    __half2 ha1 = __floats2half2_rn(fmaf(aw0, a0.z, fmaf(aw1, a1.z, aw2 * a2.z)),
                                    fmaf(aw0, a0.w, fmaf(aw1, a1.w, aw2 * a2.w)));
    __half2 hb0 = __floats2half2_rn(fmaf(bw0, b0.x, fmaf(bw1, b1.x, bw2 * b2.x)),
                                    fmaf(bw0, b0.y, fmaf(bw1, b1.y, bw2 * b2.y)));
    __half2 hb1 = __floats2half2_rn(fmaf(bw0, b0.z, fmaf(bw1, b1.z, bw2 * b2.z)),
                                    fmaf(bw0, b0.w, fmaf(bw1, b1.w, bw2 * b2.w)));
    *(uint2*)(g_interp + (size_t)ptA * C2 + c) = make_uint2(h2_bits(ha0), h2_bits(ha1));
    *(uint2*)(g_interp + (size_t)ptB * C2 + c) = make_uint2(h2_bits(hb0), h2_bits(hb1));
}

// ---------------- kernel 3: fp16 m16n8k16 mma GEMM, 3-stage cp.async ----------------
// grid = b(16) x Mtile(2) x Ntile(2) x splitK(4) = 256 CTAs, 256 threads
__global__ __launch_bounds__(256, 2)
void gemm_mma_kernel() {
    extern __shared__ char smc[];
    const uint32_t smb = smem_u32(smc);

    int bid = blockIdx.x;
    int s   = bid & 3;
    int mtb = (bid >> 2) & 1;
    int ntb = (bid >> 3) & 1;
    int b   = bid >> 4;
    int o0 = mtb * 128, c0 = ntb * 128, k0 = s * KPER;

    int t = threadIdx.x;
    int w = t >> 5, lane = t & 31;
    int g = lane >> 2, kq = lane & 3;
    int warp_m = (w & 3) * 32;
    int warp_n = (w >> 2) * 64;

    const __half* Wg = g_Whf + (size_t)o0 * KTOT + k0;
    const __half* Bg = g_interp + ((size_t)b * N1 + k0) * C2 + c0;

    int wr[4], wc[4], br[4], bc[4];
    uint32_t wdst[4], bdst[4];
#pragma unroll
    for (int i = 0; i < 4; ++i) {
        int li = i * 256 + t;
        wr[i] = li >> 3;  wc[i] = li & 7;
        br[i] = li >> 4;  bc[i] = li & 15;
        wdst[i] = (uint32_t)(wr[i] * (WROW_H * 2) + wc[i] * 16);
        bdst[i] = (uint32_t)(WS_BYTES + br[i] * (BROW_H * 2) + bc[i] * 16);
    }

    int sel = lane >> 3, li8 = lane & 7;
    uint32_t aoff = (uint32_t)(((warp_m + li8 + (sel & 1) * 8) * WROW_H + (sel >> 1) * 8) * 2);
    uint32_t boff = (uint32_t)(WS_BYTES +
                    ((li8 + (sel & 1) * 8) * BROW_H + warp_n + (sel >> 1) * 8) * 2);

    float acc[2][8][4];
#pragma unroll
    for (int mt = 0; mt < 2; ++mt)
#pragma unroll
        for (int nt = 0; nt < 8; ++nt)
#pragma unroll
            for (int r = 0; r < 4; ++r) acc[mt][nt][r] = 0.f;

#pragma unroll
    for (int pre = 0; pre < 2; ++pre) {
        uint32_t sb = smb + (uint32_t)(pre * STG_BYTES);
        int kg = pre * KT;
#pragma unroll
        for (int i = 0; i < 4; ++i) {
            cp16(sb + wdst[i], Wg + (size_t)wr[i] * KTOT + kg + wc[i] * 8);
            cp16(sb + bdst[i], Bg + (size_t)(kg + br[i]) * C2 + bc[i] * 8);
        }
        CP_COMMIT();
    }

    int cur = 0;
    int nxt2 = 2 * STG_BYTES;
    for (int kt = 0; kt < NT; ++kt) {
        if (kt == NT - 1) { CP_WAIT(0); } else { CP_WAIT(1); }
        __syncthreads();

        if (kt + 2 < NT) {
            uint32_t sb = smb + (uint32_t)nxt2;
            int kg = (kt + 2) * KT;
#pragma unroll
            for (int i = 0; i < 4; ++i) {
                cp16(sb + wdst[i], Wg + (size_t)wr[i] * KTOT + kg + wc[i] * 8);
                cp16(sb + bdst[i], Bg + (size_t)(kg + br[i]) * C2 + bc[i] * 8);
            }
            CP_COMMIT();
        }

#pragma unroll
        for (int ks = 0; ks < 4; ++ks) {           // 4 x k16 per tile
            uint32_t a0[4], a1[4];
            uint32_t abase = smb + (uint32_t)cur + aoff + (uint32_t)(ks * 32);
            ldsm_x4(a0, abase);
            ldsm_x4(a1, abase + 16 * WROW_H * 2);
            uint32_t bbase = smb + (uint32_t)cur + boff + (uint32_t)(ks * 16 * BROW_H * 2);
#pragma unroll
            for (int p = 0; p < 4; ++p) {          // n-chunk pairs (16 cols each)
                uint32_t r[4];
                ldsm_x4_t(r, bbase + (uint32_t)(p * 32));
                mma_f16(acc[0][2 * p],     a0, r[0], r[1]);
                mma_f16(acc[1][2 * p],     a1, r[0], r[1]);
                mma_f16(acc[0][2 * p + 1], a0, r[2], r[3]);
                mma_f16(acc[1][2 * p + 1], a1, r[2], r[3]);
            }
        }

        cur  += STG_BYTES; if (cur  == 3 * STG_BYTES) cur  = 0;
        nxt2 += STG_BYTES; if (nxt2 == 3 * STG_BYTES) nxt2 = 0;
    }

    // epilogue -> g_yp[s]
    float* out = g_yp[s] + ((size_t)b * OUTCH + o0) * C2 + c0;
#pragma unroll
    for (int mt = 0; mt < 2; ++mt) {
        int r0 = warp_m + mt * 16 + g;
#pragma unroll
        for (int nt = 0; nt < 8; ++nt) {
            int col = warp_n + nt * 8 + kq * 2;
            *(float2*)(out + (size_t)r0 * C2 + col)       = make_float2(acc[mt][nt][0], acc[mt][nt][1]);
            *(float2*)(out + (size_t)(r0 + 8) * C2 + col) = make_float2(acc[mt][nt][2], acc[mt][nt][3]);
        }
    }
}

// ---------------- kernel 4: fused reduce + BN + ReLU (grid barrier) ----------------
// 256 blocks x 256 threads; block owns rows [bid*16, bid*16+16)
__global__ __launch_bounds__(256)
void reduce_bn_kernel(const float* __restrict__ b1,
                      const float* __restrict__ gamma,
                      const float* __restrict__ beta,
                      float* __restrict__ out) {
    __shared__ float sv[16 * 256];   // 16 KB: v for this block's rows

    int c = threadIdx.x;
    int row0 = blockIdx.x * 16;

    // phase 1: sum partials + bias, park in smem, accumulate stats
    float s1 = 0.f, s2 = 0.f;
    for (int r = 0; r < 16; ++r) {
        int row = row0 + r;
        int o = row & (OUTCH - 1);
        size_t idx = (size_t)row * C2 + c;
        float v = b1[o];
#pragma unroll
        for (int s = 0; s < SPLITK; ++s) v += g_yp[s][idx];
        sv[r * 256 + c] = v;
        s1 += v;
        s2 = fmaf(v, v, s2);
    }
    atomicAdd(&g_sum[c], s1);
    atomicAdd(&g_sumsq[c], s2);

    // grid barrier: all stats visible before phase 2
    __threadfence();
    __syncthreads();
    if (threadIdx.x == 0) {
        atomicAdd(&g_cnt, 1u);
        while (atomicAdd(&g_cnt, 0u) < RB_BLOCKS) { }
    }
    __syncthreads();
    __threadfence();

    // phase 2: normalize + relu + store
    const float invN = 1.f / (BATCH * OUTCH);
    float sm, sq;
    asm volatile("ld.global.cg.f32 %0, [%1];" : "=f"(sm) : "l"(&g_sum[c]));
    asm volatile("ld.global.cg.f32 %0, [%1];" : "=f"(sq) : "l"(&g_sumsq[c]));
    float mean = sm * invN;
    float var  = fmaf(sq, invN, -mean * mean);
    float scale = gamma[c] * rsqrtf(var + BN_EPS);
    float shift = beta[c];
#pragma unroll
    for (int r = 0; r < 16; ++r) {
        float v = sv[r * 256 + c];
        float o = fmaf(scale, v - mean, shift);
        out[(size_t)(row0 + r) * C2 + c] = fmaxf(o, 0.f);
    }
}

// ---------------- launcher ----------------
extern "C" void kernel_launch(void* const* d_in, const int* in_sizes, int n_in,
                              void* d_out, int out_size) {
    const float* x2    = (const float*)d_in[1];
    const float* xyz1  = (const float*)d_in[2];
    const float* xyz2  = (const float*)d_in[3];
    const float* W1    = (const float*)d_in[4];
    const float* b1    = (const float*)d_in[5];
    const float* gamma = (const float*)d_in[6];
    const float* beta  = (const float*)d_in[7];
    float* out = (float*)d_out;

    cudaFuncSetAttribute(gemm_mma_kernel,
                         cudaFuncAttributeMaxDynamicSharedMemorySize,
                         SMEM_BYTES);

    convW_kernel<<<(OUTCH * KTOT) / 1024, 256>>>(W1);
    topk_kernel<<<BATCH * 16, 256>>>(xyz1, xyz2);
    interp_kernel<<<(BATCH * N1) / 8, 256>>>(x2);
    gemm_mma_kernel<<<BATCH * 2 * 2 * SPLITK, 256, SMEM_BYTES>>>();
    reduce_bn_kernel<<<RB_BLOCKS, 256>>>(b1, gamma, beta, out);
}

// round 17
// speedup vs baseline: 1.4456x; 1.0088x over previous
#include <cuda_runtime.h>
#include <cuda_fp16.h>
#include <cstdint>

// ---------------- problem constants ----------------
#define BATCH   16
#define N1      4096
#define N2      1024
#define C2      256
#define OUTCH   256
#define KTOT    4096
#define SPLITK  4
#define KPER    (KTOT/SPLITK)   // 1024
#define KT      64              // K tile
#define NT      (KPER/KT)       // 16 tiles
#define BN_EPS  1e-5f

#define NBLK 256                // megakernel grid

// smem (bytes): 3 stages of (W 128x72 halves + B 64x136 halves)
#define WROW_H   72
#define BROW_H   136
#define WS_BYTES (128*WROW_H*2)  // 18432
#define BS_BYTES (64*BROW_H*2)   // 17408
#define STG_BYTES (WS_BYTES + BS_BYTES)   // 35840
#define SMEM_BYTES (3*STG_BYTES)          // 107520

// ---------------- device scratch ----------------
__device__ int    g_idx[BATCH * N1 * 3];
__device__ float  g_w  [BATCH * N1 * 3];
__device__ __half g_Whf[(size_t)OUTCH * KTOT];                 // 2 MB fp16 W
__device__ __half g_interp[(size_t)BATCH * N1 * C2];           // 33.5 MB fp16 A[b][n][c]
__device__ float  g_yp[SPLITK][(size_t)BATCH * OUTCH * C2];    // 16 MB fp32 partials
__device__ float  g_sum[C2];
__device__ float  g_sumsq[C2];
__device__ unsigned int g_bar[4];                              // monotonic barrier counters

// ---------------- helpers ----------------
__device__ __forceinline__ uint32_t smem_u32(const void* p) {
    uint32_t a;
    asm("{ .reg .u64 t; cvta.to.shared.u64 t, %1; cvt.u32.u64 %0, t; }" : "=r"(a) : "l"(p));
    return a;
}
__device__ __forceinline__ uint32_t h2_bits(__half2 h) {
    uint32_t u;
    memcpy(&u, &h, 4);
    return u;
}
__device__ __forceinline__ void cp16(uint32_t dst, const void* src) {
    asm volatile("cp.async.cg.shared.global [%0], [%1], 16;" :: "r"(dst), "l"(src) : "memory");
}
#define CP_COMMIT()  asm volatile("cp.async.commit_group;" ::: "memory")
#define CP_WAIT(n)   asm volatile("cp.async.wait_group %0;" :: "n"(n) : "memory")

__device__ __forceinline__ void ldsm_x4(uint32_t* r, uint32_t addr) {
    asm volatile("ldmatrix.sync.aligned.m8n8.x4.shared.b16 {%0,%1,%2,%3}, [%4];"
                 : "=r"(r[0]), "=r"(r[1]), "=r"(r[2]), "=r"(r[3]) : "r"(addr));
}
__device__ __forceinline__ void ldsm_x4_t(uint32_t* r, uint32_t addr) {
    asm volatile("ldmatrix.sync.aligned.m8n8.x4.trans.shared.b16 {%0,%1,%2,%3}, [%4];"
                 : "=r"(r[0]), "=r"(r[1]), "=r"(r[2]), "=r"(r[3]) : "r"(addr));
}
__device__ __forceinline__ void mma_f16(float* d, const uint32_t* a, uint32_t b0, uint32_t b1) {
    asm volatile(
        "mma.sync.aligned.m16n8k16.row.col.f32.f16.f16.f32 "
        "{%0,%1,%2,%3}, {%4,%5,%6,%7}, {%8,%9}, {%0,%1,%2,%3};"
        : "+f"(d[0]), "+f"(d[1]), "+f"(d[2]), "+f"(d[3])
        : "r"(a[0]), "r"(a[1]), "r"(a[2]), "r"(a[3]), "r"(b0), "r"(b1));
}

// monotonic grid barrier: never reset, safe across graph replays
__device__ __forceinline__ void grid_barrier(int k) {
    __syncthreads();
    if (threadIdx.x == 0) {
        __threadfence();
        unsigned int ticket = atomicAdd(&g_bar[k], 1u);
        unsigned int target = (ticket / NBLK + 1u) * NBLK;
        while (atomicAdd(&g_bar[k], 0u) < target) { }
        __threadfence();
    }
    __syncthreads();
}

// ---------------- megakernel: convW+topk | interp | gemm | reduce+bn ----------------
__global__ __launch_bounds__(256, 2)
void mega_kernel(const float* __restrict__ W1,
                 const float* __restrict__ x2,
                 const float* __restrict__ xyz1,
                 const float* __restrict__ xyz2,
                 const float* __restrict__ b1,
                 const float* __restrict__ gamma,
                 const float* __restrict__ beta,
                 float* __restrict__ out) {
    extern __shared__ char smc[];
    int blk = blockIdx.x;
    int t   = threadIdx.x;

    // ================= P0a: convW (fp32 -> fp16) + stats zero =================
    {
        const float4* src = (const float4*)W1;
        int base = blk * 1024 + t;          // 262144 float4 total / 256 blocks
#pragma unroll
        for (int i = 0; i < 4; ++i) {
            int idx = base + i * 256;
            float4 v = src[idx];
            __half2 h0 = __floats2half2_rn(v.x, v.y);
            __half2 h1 = __floats2half2_rn(v.z, v.w);
            ((uint2*)g_Whf)[idx] = make_uint2(h2_bits(h0), h2_bits(h1));
        }
        if (blk == 0) {
            g_sum[t] = 0.f;
            g_sumsq[t] = 0.f;
        }
    }

    // ================= P0b: topk =================
    {
        float4* sq = (float4*)smc;          // 1024 x 16B = 16 KB
        int b = blk >> 4;
        int nchunk = blk & 15;

        const float* p2 = xyz2 + (size_t)b * N2 * 3;
        for (int j = t; j < N2; j += 256) {
            float qx = p2[j * 3 + 0], qy = p2[j * 3 + 1], qz = p2[j * 3 + 2];
            sq[j] = make_float4(qx, qy, qz, fmaf(qx, qx, fmaf(qy, qy, qz * qz)));
        }
        __syncthreads();

        int n = nchunk * 256 + t;
        const float* p1 = xyz1 + ((size_t)b * N1 + n) * 3;
        float px = p1[0], py = p1[1], pz = p1[2];
        float px2 = -2.f * px, py2 = -2.f * py, pz2 = -2.f * pz;
        float pp = fmaf(px, px, fmaf(py, py, pz * pz));

        float d0 = 3.4e38f, d1 = 3.4e38f, d2 = 3.4e38f;
        int   i0 = 0, i1 = 0, i2 = 0;
#pragma unroll 8
        for (int j = 0; j < N2; ++j) {
            float4 q = sq[j];
            float d = fmaf(px2, q.x, fmaf(py2, q.y, fmaf(pz2, q.z, q.w)));
            if (d < d2) {
                if (d < d1) {
                    d2 = d1; i2 = i1;
                    if (d < d0) { d1 = d0; i1 = i0; d0 = d; i0 = j; }
                    else        { d1 = d;  i1 = j; }
                } else { d2 = d; i2 = j; }
            }
        }
        float r0 = 1.f / (d0 + pp + 1e-8f);
        float r1 = 1.f / (d1 + pp + 1e-8f);
        float r2 = 1.f / (d2 + pp + 1e-8f);
        float inv = 1.f / (r0 + r1 + r2);
        size_t base = ((size_t)b * N1 + n) * 3;
        g_idx[base + 0] = i0; g_idx[base + 1] = i1; g_idx[base + 2] = i2;
        g_w  [base + 0] = r0 * inv; g_w[base + 1] = r1 * inv; g_w[base + 2] = r2 * inv;
    }

    grid_barrier(0);

    // ================= P1: interp (points [blk*256, blk*256+256)) =================
    {
        int pair = t >> 6;            // 0..3
        int lane = t & 63;
        int c = lane * 4;
#pragma unroll 2
        for (int it = 0; it < 32; ++it) {
            int ptA = blk * 256 + it * 8 + pair * 2;
            int ptB = ptA + 1;
            int b = ptA >> 12;

            size_t baseA = (size_t)ptA * 3, baseB = (size_t)ptB * 3;
            int ai0 = g_idx[baseA + 0], ai1 = g_idx[baseA + 1], ai2 = g_idx[baseA + 2];
            int bi0 = g_idx[baseB + 0], bi1 = g_idx[baseB + 1], bi2 = g_idx[baseB + 2];
            float aw0 = g_w[baseA + 0], aw1 = g_w[baseA + 1], aw2 = g_w[baseA + 2];
            float bw0 = g_w[baseB + 0], bw1 = g_w[baseB + 1], bw2 = g_w[baseB + 2];

            const float* xb = x2 + (size_t)b * N2 * C2 + c;
            float4 a0 = *(const float4*)(xb + (size_t)ai0 * C2);
            float4 a1 = *(const float4*)(xb + (size_t)ai1 * C2);
            float4 a2 = *(const float4*)(xb + (size_t)ai2 * C2);
            float4 b0 = *(const float4*)(xb + (size_t)bi0 * C2);
            float4 b1 = *(const float4*)(xb + (size_t)bi1 * C2);
            float4 b2 = *(const float4*)(xb + (size_t)bi2 * C2);

            __half2 ha0 = __floats2half2_rn(fmaf(aw0, a0.x, fmaf(aw1, a1.x, aw2 * a2.x)),
                                            fmaf(aw0, a0.y, fmaf(aw1, a1.y, aw2 * a2.y)));
            __half2 ha1 = __floats2half2_rn(fmaf(aw0, a0.z, fmaf(aw1, a1.z, aw2 * a2.z)),
                                            fmaf(aw0, a0.w, fmaf(aw1, a1.w, aw2 * a2.w)));
            __half2 hb0 = __floats2half2_rn(fmaf(bw0, b0.x, fmaf(bw1, b1.x, bw2 * b2.x)),
                                            fmaf(bw0, b0.y, fmaf(bw1, b1.y, bw2 * b2.y)));
            __half2 hb1 = __floats2half2_rn(fmaf(bw0, b0.z, fmaf(bw1, b1.z, bw2 * b2.z)),
                                            fmaf(bw0, b0.w, fmaf(bw1, b1.w, bw2 * b2.w)));
            *(uint2*)(g_interp + (size_t)ptA * C2 + c) = make_uint2(h2_bits(ha0), h2_bits(ha1));
            *(uint2*)(g_interp + (size_t)ptB * C2 + c) = make_uint2(h2_bits(hb0), h2_bits(hb1));
        }
    }

    grid_barrier(1);

    // ================= P2: GEMM (fp16 m16n8k16, 3-stage cp.async) =================
    {
        const uint32_t smb = smem_u32(smc);

        int s   = blk & 3;
        int mtb = (blk >> 2) & 1;
        int ntb = (blk >> 3) & 1;
        int b   = blk >> 4;
        int o0 = mtb * 128, c0 = ntb * 128, k0 = s * KPER;

        int w = t >> 5, lane = t & 31;
        int g = lane >> 2, kq = lane & 3;
        int warp_m = (w & 3) * 32;
        int warp_n = (w >> 2) * 64;

        const __half* Wg = g_Whf + (size_t)o0 * KTOT + k0;
        const __half* Bg = g_interp + ((size_t)b * N1 + k0) * C2 + c0;

        int wr[4], wc[4], br[4], bc[4];
        uint32_t wdst[4], bdst[4];
#pragma unroll
        for (int i = 0; i < 4; ++i) {
            int li = i * 256 + t;
            wr[i] = li >> 3;  wc[i] = li & 7;
            br[i] = li >> 4;  bc[i] = li & 15;
            wdst[i] = (uint32_t)(wr[i] * (WROW_H * 2) + wc[i] * 16);
            bdst[i] = (uint32_t)(WS_BYTES + br[i] * (BROW_H * 2) + bc[i] * 16);
        }

        int sel = lane >> 3, li8 = lane & 7;
        uint32_t aoff = (uint32_t)(((warp_m + li8 + (sel & 1) * 8) * WROW_H + (sel >> 1) * 8) * 2);
        uint32_t boff = (uint32_t)(WS_BYTES +
                        ((li8 + (sel & 1) * 8) * BROW_H + warp_n + (sel >> 1) * 8) * 2);

        float acc[2][8][4];
#pragma unroll
        for (int mt = 0; mt < 2; ++mt)
#pragma unroll
            for (int nt = 0; nt < 8; ++nt)
#pragma unroll
                for (int r = 0; r < 4; ++r) acc[mt][nt][r] = 0.f;

#pragma unroll
        for (int pre = 0; pre < 2; ++pre) {
            uint32_t sb = smb + (uint32_t)(pre * STG_BYTES);
            int kg = pre * KT;
#pragma unroll
            for (int i = 0; i < 4; ++i) {
                cp16(sb + wdst[i], Wg + (size_t)wr[i] * KTOT + kg + wc[i] * 8);
                cp16(sb + bdst[i], Bg + (size_t)(kg + br[i]) * C2 + bc[i] * 8);
            }
            CP_COMMIT();
        }

        int cur = 0;
        int nxt2 = 2 * STG_BYTES;
        for (int kt = 0; kt < NT; ++kt) {
            if (kt == NT - 1) { CP_WAIT(0); } else { CP_WAIT(1); }
            __syncthreads();

            if (kt + 2 < NT) {
                uint32_t sb = smb + (uint32_t)nxt2;
                int kg = (kt + 2) * KT;
#pragma unroll
                for (int i = 0; i < 4; ++i) {
                    cp16(sb + wdst[i], Wg + (size_t)wr[i] * KTOT + kg + wc[i] * 8);
                    cp16(sb + bdst[i], Bg + (size_t)(kg + br[i]) * C2 + bc[i] * 8);
                }
                CP_COMMIT();
            }

#pragma unroll
            for (int ks = 0; ks < 4; ++ks) {
                uint32_t a0[4], a1[4];
                uint32_t abase = smb + (uint32_t)cur + aoff + (uint32_t)(ks * 32);
                ldsm_x4(a0, abase);
                ldsm_x4(a1, abase + 16 * WROW_H * 2);
                uint32_t bbase = smb + (uint32_t)cur + boff + (uint32_t)(ks * 16 * BROW_H * 2);
#pragma unroll
                for (int p = 0; p < 4; ++p) {
                    uint32_t r[4];
                    ldsm_x4_t(r, bbase + (uint32_t)(p * 32));
                    mma_f16(acc[0][2 * p],     a0, r[0], r[1]);
                    mma_f16(acc[1][2 * p],     a1, r[0], r[1]);
                    mma_f16(acc[0][2 * p + 1], a0, r[2], r[3]);
                    mma_f16(acc[1][2 * p + 1], a1, r[2], r[3]);
                }
            }

            cur  += STG_BYTES; if (cur  == 3 * STG_BYTES) cur  = 0;
            nxt2 += STG_BYTES; if (nxt2 == 3 * STG_BYTES) nxt2 = 0;
        }

        float* outp = g_yp[s] + ((size_t)b * OUTCH + o0) * C2 + c0;
#pragma unroll
        for (int mt = 0; mt < 2; ++mt) {
            int r0 = warp_m + mt * 16 + g;
#pragma unroll
            for (int nt = 0; nt < 8; ++nt) {
                int col = warp_n + nt * 8 + kq * 2;
                *(float2*)(outp + (size_t)r0 * C2 + col)       = make_float2(acc[mt][nt][0], acc[mt][nt][1]);
                *(float2*)(outp + (size_t)(r0 + 8) * C2 + col) = make_float2(acc[mt][nt][2], acc[mt][nt][3]);
            }
        }
    }

    grid_barrier(2);

    // ================= P3/P4: reduce + BN + ReLU =================
    {
        float* sv = (float*)smc;   // 16 rows x 256 ch = 16 KB
        int c = t;
        int row0 = blk * 16;

        float s1 = 0.f, s2 = 0.f;
        for (int r = 0; r < 16; ++r) {
            int row = row0 + r;
            int o = row & (OUTCH - 1);
            size_t idx = (size_t)row * C2 + c;
            float v = b1[o];
#pragma unroll
            for (int s = 0; s < SPLITK; ++s) v += g_yp[s][idx];
            sv[r * 256 + c] = v;
            s1 += v;
            s2 = fmaf(v, v, s2);
        }
        atomicAdd(&g_sum[c], s1);
        atomicAdd(&g_sumsq[c], s2);

        grid_barrier(3);

        const float invN = 1.f / (BATCH * OUTCH);
        float sm, sq;
        asm volatile("ld.global.cg.f32 %0, [%1];" : "=f"(sm) : "l"(&g_sum[c]));
        asm volatile("ld.global.cg.f32 %0, [%1];" : "=f"(sq) : "l"(&g_sumsq[c]));
        float mean = sm * invN;
        float var  = fmaf(sq, invN, -mean * mean);
        float scale = gamma[c] * rsqrtf(var + BN_EPS);
        float shift = beta[c];
#pragma unroll
        for (int r = 0; r < 16; ++r) {
            float v = sv[r * 256 + c];
            float o = fmaf(scale, v - mean, shift);
            out[(size_t)(row0 + r) * C2 + c] = fmaxf(o, 0.f);
        }
    }
}

// ---------------- launcher ----------------
extern "C" void kernel_launch(void* const* d_in, const int* in_sizes, int n_in,
                              void* d_out, int out_size) {
    const float* x2    = (const float*)d_in[1];
    const float* xyz1  = (const float*)d_in[2];
    const float* xyz2  = (const float*)d_in[3];
    const float* W1    = (const float*)d_in[4];
    const float* b1    = (const float*)d_in[5];
    const float* gamma = (const float*)d_in[6];
    const float* beta  = (const float*)d_in[7];
    float* out = (float*)d_out;

    cudaFuncSetAttribute(mega_kernel,
                         cudaFuncAttributeMaxDynamicSharedMemorySize,
                         SMEM_BYTES);

    mega_kernel<<<NBLK, 256, SMEM_BYTES>>>(W1, x2, xyz1, xyz2, b1, gamma, beta, out);
}